// round 11
// baseline (speedup 1.0000x reference)
#include <cuda_runtime.h>
#include <cuda_bf16.h>
#include <cstdint>

// ---------------------------------------------------------------------------
// LinkWeightDecoder: out[e] = MLP(concat(emb[src_e], emb[dst_e]))
//   K1 (mma.sync bf16 hi/lo): P[n][0:256] = emb[n] @ [W1a|W1b] (+b1 on first half)
//   K2 (mma.sync bf16 hi/lo): 128-edge tiles, 4 warps x 32 edges (M=32),
//     fused 3-pass GEMM (Ahi·Bhi + Alo·Bhi + Ahi·Blo), fp32 acc in regs,
//     out[e]=sum_j relu(D[e][j]+b2[j])*W3[j]+b3.
//   XOR-compressed ldmatrix addresses; B fragments amortized over 32 edges.
// ---------------------------------------------------------------------------

#define MAXN 100000
#define NSM  148

__device__ float g_P[MAXN * 256];   // per-node projections (102.4 MB)

// ---------------- helpers ----------------
__device__ __forceinline__ uint32_t smem_u32(const void* p) {
    uint32_t a;
    asm("{ .reg .u64 t; cvta.to.shared.u64 t, %1; cvt.u32.u64 %0, t; }"
        : "=r"(a) : "l"(p));
    return a;
}
#define SWZ(off) ((off) ^ (((off) >> 3) & 0x70))

__device__ __forceinline__ void ldsm4(uint32_t* r, uint32_t addr) {
    asm volatile("ldmatrix.sync.aligned.m8n8.x4.shared.b16 {%0,%1,%2,%3}, [%4];"
        : "=r"(r[0]), "=r"(r[1]), "=r"(r[2]), "=r"(r[3]) : "r"(addr));
}
__device__ __forceinline__ void ldsm4t(uint32_t* r, uint32_t addr) {
    asm volatile("ldmatrix.sync.aligned.m8n8.x4.trans.shared.b16 {%0,%1,%2,%3}, [%4];"
        : "=r"(r[0]), "=r"(r[1]), "=r"(r[2]), "=r"(r[3]) : "r"(addr));
}
__device__ __forceinline__ void mma16816(float* c, const uint32_t* a,
                                         uint32_t b0, uint32_t b1) {
    asm volatile(
        "mma.sync.aligned.m16n8k16.row.col.f32.bf16.bf16.f32 "
        "{%0,%1,%2,%3}, {%4,%5,%6,%7}, {%8,%9}, {%0,%1,%2,%3};"
        : "+f"(c[0]), "+f"(c[1]), "+f"(c[2]), "+f"(c[3])
        : "r"(a[0]), "r"(a[1]), "r"(a[2]), "r"(a[3]), "r"(b0), "r"(b1));
}
// split fp32 quad -> bf16 hi/lo packed uint2
__device__ __forceinline__ void split4(float4 h, uint2& uhi, uint2& ulo) {
    __nv_bfloat162 h01 = __float22bfloat162_rn(make_float2(h.x, h.y));
    __nv_bfloat162 h23 = __float22bfloat162_rn(make_float2(h.z, h.w));
    float2 f01 = __bfloat1622float2(h01);
    float2 f23 = __bfloat1622float2(h23);
    __nv_bfloat162 l01 = __float22bfloat162_rn(make_float2(h.x - f01.x, h.y - f01.y));
    __nv_bfloat162 l23 = __float22bfloat162_rn(make_float2(h.z - f23.x, h.w - f23.y));
    uhi.x = *(uint32_t*)&h01; uhi.y = *(uint32_t*)&h23;
    ulo.x = *(uint32_t*)&l01; ulo.y = *(uint32_t*)&l23;
}

// ---------------------------------------------------------------------------
// Kernel 1 (persistent, HMMA): P = emb @ [W1a|W1b] (+b1 fold on cols<128)
// (unchanged from passing round 9/10)
// ---------------------------------------------------------------------------
#define PA_HI 0
#define PA_LO 32768
#define PB_HI 65536
#define PB_LO 131072
#define PB1   196608
#define PRE_SMEM_BYTES (196608 + 1024)

__global__ __launch_bounds__(256, 1)
void precompute_kernel(const float* __restrict__ emb,
                       const float* __restrict__ W1,
                       const float* __restrict__ b1, int N, int nTiles) {
    extern __shared__ char smem[];
    const uint32_t sbase = smem_u32(smem);
    float* sB1 = (float*)(smem + PB1);

    const int tid  = threadIdx.x;
    const int lane = tid & 31, w = tid >> 5;

#pragma unroll 4
    for (int it = 0; it < 32; it++) {
        int idx = it * 256 + tid;
        int k = idx >> 6, og4 = (idx & 63) * 4;
        const float* sp = (og4 < 128) ? &W1[k * 128 + og4]
                                      : &W1[(k + 128) * 128 + (og4 - 128)];
        float4 v = *(const float4*)sp;
        uint2 uhi, ulo;
        split4(v, uhi, ulo);
        int c = og4 >> 6, o = og4 & 63;
        uint32_t off = c * 16384 + SWZ((uint32_t)(k * 128 + o * 2));
        *(uint2*)(smem + PB_HI + off) = uhi;
        *(uint2*)(smem + PB_LO + off) = ulo;
    }
    sB1[tid] = (tid < 128) ? b1[tid] : 0.f;
    __syncthreads();

    const int aRow  = w * 16 + (lane & 15);
    const int aHalf = (lane >> 4) * 16;
    const int bKrow = (lane & 7) + ((lane >> 3) & 1) * 8;
    const int bHalf = (lane >> 4) * 16;
    const int g = lane >> 2, tq = lane & 3;

    const float4* E4 = (const float4*)emb;
    const int grid = gridDim.x;

    for (int t = blockIdx.x; t < nTiles; t += grid) {
#pragma unroll 4
        for (int i = 0; i < 16; i++) {
            int row = w * 16 + i;
            int node = t * 128 + row; if (node >= N) node = N - 1;
            float4 v = __ldg(&E4[(long long)node * 32 + lane]);
            uint2 uhi, ulo;
            split4(v, uhi, ulo);
            int sub = lane >> 4;
            uint32_t boff = SWZ((uint32_t)(row * 128 + (lane & 15) * 8));
            char* pa = smem + sub * 16384 + boff;
            *(uint2*)(pa + PA_HI) = uhi;
            *(uint2*)(pa + PA_LO) = ulo;
        }
        __syncwarp();

#pragma unroll 1
        for (int c = 0; c < 4; c++) {
            const uint32_t bHi = sbase + PB_HI + c * 16384;
            const uint32_t bLo = sbase + PB_LO + c * 16384;

            uint32_t Ahi[8][4];
#pragma unroll
            for (int ks = 0; ks < 8; ks++) {
                uint32_t raw = (uint32_t)(aRow * 128 + (ks & 3) * 32 + aHalf);
                ldsm4(Ahi[ks], sbase + PA_HI + (ks >> 2) * 16384 + SWZ(raw));
            }

            float acc[8][4];
#pragma unroll
            for (int nf = 0; nf < 8; nf++)
#pragma unroll
                for (int p = 0; p < 4; p++) acc[nf][p] = 0.f;

#pragma unroll 2
            for (int ks = 0; ks < 8; ks++) {
                uint32_t Alo[4];
                uint32_t rawA = (uint32_t)(aRow * 128 + (ks & 3) * 32 + aHalf);
                ldsm4(Alo, sbase + PA_LO + (ks >> 2) * 16384 + SWZ(rawA));
#pragma unroll
                for (int nb = 0; nb < 4; nb++) {
                    uint32_t bfr[4];
                    uint32_t rawB = (uint32_t)((ks * 16 + bKrow) * 128 + nb * 32 + bHalf);
                    ldsm4t(bfr, bHi + SWZ(rawB));
                    mma16816(acc[2 * nb],     Ahi[ks], bfr[0], bfr[1]);
                    mma16816(acc[2 * nb + 1], Ahi[ks], bfr[2], bfr[3]);
                    mma16816(acc[2 * nb],     Alo,     bfr[0], bfr[1]);
                    mma16816(acc[2 * nb + 1], Alo,     bfr[2], bfr[3]);
                }
            }
#pragma unroll 2
            for (int ks = 0; ks < 8; ks++) {
#pragma unroll
                for (int nb = 0; nb < 4; nb++) {
                    uint32_t bfr[4];
                    uint32_t rawB = (uint32_t)((ks * 16 + bKrow) * 128 + nb * 32 + bHalf);
                    ldsm4t(bfr, bLo + SWZ(rawB));
                    mma16816(acc[2 * nb],     Ahi[ks], bfr[0], bfr[1]);
                    mma16816(acc[2 * nb + 1], Ahi[ks], bfr[2], bfr[3]);
                }
            }

            int n1 = t * 128 + w * 16 + g;
            int n2 = n1 + 8;
#pragma unroll
            for (int nf = 0; nf < 8; nf++) {
                int o = c * 64 + nf * 8 + tq * 2;
                float2 bias = *(const float2*)&sB1[o];
                if (n1 < N) {
                    float2 r = make_float2(acc[nf][0] + bias.x, acc[nf][1] + bias.y);
                    *(float2*)&g_P[(long long)n1 * 256 + o] = r;
                }
                if (n2 < N) {
                    float2 r = make_float2(acc[nf][2] + bias.x, acc[nf][3] + bias.y);
                    *(float2*)&g_P[(long long)n2 * 256 + o] = r;
                }
            }
        }
        __syncwarp();
    }
}

// ---------------------------------------------------------------------------
// Kernel 2: persistent HMMA, 128-edge tiles, 4 warps x 32 edges (M=32).
// 128 threads/block, 2 blocks/SM (256-reg cap -> 64 accumulators fit).
// B fragments amortized over 32 edges: 96 ldsm per warp-tile (was 160/32e).
// ---------------------------------------------------------------------------
#define A_HI_OFF 0
#define A_LO_OFF 32768
#define B_HI_OFF 65536
#define B_LO_OFF 81920
#define SBW_OFF  98304
#define EDGE_SMEM_BYTES (98304 + 512 + 1024)

__global__ __launch_bounds__(128, 2)
void edge_kernel(const int* __restrict__ eidx_w,
                 const float* __restrict__ W2,
                 const float* __restrict__ b2,
                 const float* __restrict__ W3,
                 const float* __restrict__ b3,
                 float* __restrict__ out, int E, int N, int nTiles) {
    extern __shared__ char smem_raw[];
    char* sm = (char*)(((uintptr_t)smem_raw + 1023) & ~(uintptr_t)1023);
    const uint32_t sbase = smem_u32(sm);
    float4* sBW4 = (float4*)(sm + SBW_OFF);
    __shared__ int sAny;

    const int tid  = threadIdx.x;
    const int lane = tid & 31, w = tid >> 5;   // w in 0..3

    // ---- one-time: dtype detect, W2 hi/lo staging, b2/W3 staging ----
    if (tid == 0) sAny = 0;
    __syncthreads();
    if (tid < 64 && eidx_w[2 * tid + 1] != 0) atomicOr(&sAny, 1);

#pragma unroll 4
    for (int it = 0; it < 64; it++) {
        int slot = it * 128 + tid;
        int k = slot >> 6, o = slot & 63;
        float wv = W2[k * 64 + o];
        __nv_bfloat16 hi = __float2bfloat16_rn(wv);
        __nv_bfloat16 lo = __float2bfloat16_rn(wv - __bfloat162float(hi));
        uint32_t off = SWZ((uint32_t)(k * 128 + o * 2));
        *(__nv_bfloat16*)(sm + B_HI_OFF + off) = hi;
        *(__nv_bfloat16*)(sm + B_LO_OFF + off) = lo;
    }
    if (tid < 32)
        sBW4[tid] = make_float4(b2[2 * tid], W3[2 * tid],
                                b2[2 * tid + 1], W3[2 * tid + 1]);
    __syncthreads();

    const int stride = sAny ? 1 : 2;
    const float bias3 = __ldg(&b3[0]);
    const char* Pb = (const char*)g_P;
    const int grid = gridDim.x;

    // ---- fragment geometry ----
    const int aHalf = (lane >> 4) * 16;
    const int bKrow = (lane & 7) + ((lane >> 3) & 1) * 8;
    const int bHalf = (lane >> 4) * 16;
    const int g = lane >> 2, tq = lane & 3;

    // XOR-compressed bases.
    // A m-block0: addr(ks) = (aBase0 + (ks>>2)*16384) ^ ((ks&3)<<5); mb1 = +2048
    const uint32_t Ra = (uint32_t)((w * 32 + (lane & 15)) * 128);
    const uint32_t aBase0 = sbase + A_HI_OFF + Ra
                          + ((uint32_t)aHalf ^ ((Ra >> 3) & 0x70));
    // B: addr(ks,nb) = (bBase0 + ks*2048) ^ (nb<<5); lo = +16384
    const uint32_t Rb = (uint32_t)(bKrow * 128);
    const uint32_t bBase0 = sbase + B_HI_OFF + Rb
                          + ((uint32_t)bHalf ^ ((Rb >> 3) & 0x70));

    // index loader: warp w owns edges t*128 + w*32 .. +31 (one per lane)
    auto load_idx = [&](int t, int& iS, int& iD) {
        int e = t * 128 + w * 32 + lane; if (e >= E) e = E - 1;
        int vs = eidx_w[(long long)e * stride];
        int vd = eidx_w[((long long)E + e) * stride];
        iS = min(max(vs, 0), N - 1);
        iD = min(max(vd, 0), N - 1);
    };

    int t = blockIdx.x;
    int idxS = 0, idxD = 0;
    if (t < nTiles) load_idx(t, idxS, idxD);

    for (; t < nTiles; t += grid) {
        // ---- gather + relu + bf16 hi/lo -> own 32 A rows ----
#pragma unroll 4
        for (int i = 0; i < 32; i++) {
            int si = __shfl_sync(0xffffffffu, idxS, i);
            int di = __shfl_sync(0xffffffffu, idxD, i);
            float4 a = __ldg((const float4*)(Pb + (uint32_t)si * 1024u
                                                + (uint32_t)(lane * 16)));
            float4 b = __ldg((const float4*)(Pb + (uint32_t)di * 1024u + 512u
                                                + (uint32_t)(lane * 16)));
            float4 h;
            h.x = fmaxf(a.x + b.x, 0.f);
            h.y = fmaxf(a.y + b.y, 0.f);
            h.z = fmaxf(a.z + b.z, 0.f);
            h.w = fmaxf(a.w + b.w, 0.f);
            uint2 uhi, ulo;
            split4(h, uhi, ulo);

            int row = w * 32 + i;
            int sub = lane >> 4;
            uint32_t boff = SWZ((uint32_t)(row * 128 + (lane & 15) * 8));
            char* pa = sm + sub * 16384 + boff;
            *(uint2*)(pa + A_HI_OFF) = uhi;
            *(uint2*)(pa + A_LO_OFF) = ulo;
        }
        __syncwarp();

        // ---- prefetch next tile's indices (hidden under MMA) ----
        int tn = t + grid;
        int nS = 0, nD = 0;
        if (tn < nTiles) load_idx(tn, nS, nD);

        // ---- fused 3-pass GEMM: M=32 (2 m-blocks), N=64, K=128 ----
        float acc[2][8][4];
#pragma unroll
        for (int mb = 0; mb < 2; mb++)
#pragma unroll
            for (int nf = 0; nf < 8; nf++)
#pragma unroll
                for (int p = 0; p < 4; p++) acc[mb][nf][p] = 0.f;

#pragma unroll
        for (int ks = 0; ks < 8; ks++) {
            uint32_t aH0[4], aH1[4], aL0[4], aL1[4];
            uint32_t aA = (aBase0 + ((ks >> 2) * 16384)) ^ ((ks & 3) << 5);
            ldsm4(aH0, aA);
            ldsm4(aH1, aA + 2048);
            ldsm4(aL0, aA + 32768);
            ldsm4(aL1, aA + 32768 + 2048);
            uint32_t bRow = bBase0 + (uint32_t)(ks * 2048);
#pragma unroll
            for (int nb = 0; nb < 4; nb++) {
                uint32_t bh[4], bl[4];
                uint32_t bA = bRow ^ (nb << 5);
                ldsm4t(bh, bA);
                ldsm4t(bl, bA + 16384);
                mma16816(acc[0][2 * nb],     aH0, bh[0], bh[1]);
                mma16816(acc[0][2 * nb + 1], aH0, bh[2], bh[3]);
                mma16816(acc[1][2 * nb],     aH1, bh[0], bh[1]);
                mma16816(acc[1][2 * nb + 1], aH1, bh[2], bh[3]);
                mma16816(acc[0][2 * nb],     aL0, bh[0], bh[1]);
                mma16816(acc[0][2 * nb + 1], aL0, bh[2], bh[3]);
                mma16816(acc[1][2 * nb],     aL1, bh[0], bh[1]);
                mma16816(acc[1][2 * nb + 1], aL1, bh[2], bh[3]);
                mma16816(acc[0][2 * nb],     aH0, bl[0], bl[1]);
                mma16816(acc[0][2 * nb + 1], aH0, bl[2], bl[3]);
                mma16816(acc[1][2 * nb],     aH1, bl[0], bl[1]);
                mma16816(acc[1][2 * nb + 1], aH1, bl[2], bl[3]);
            }
        }

        // ---- epilogue: +b2, relu, dot W3, 4-lane reduce, store ----
#pragma unroll
        for (int mb = 0; mb < 2; mb++) {
            float s1 = 0.f, s2 = 0.f;
#pragma unroll
            for (int nf = 0; nf < 8; nf++) {
                float4 bw = sBW4[nf * 4 + tq];
                s1 += fmaxf(acc[mb][nf][0] + bw.x, 0.f) * bw.y
                    + fmaxf(acc[mb][nf][1] + bw.z, 0.f) * bw.w;
                s2 += fmaxf(acc[mb][nf][2] + bw.x, 0.f) * bw.y
                    + fmaxf(acc[mb][nf][3] + bw.z, 0.f) * bw.w;
            }
            s1 += __shfl_xor_sync(0xffffffffu, s1, 1);
            s1 += __shfl_xor_sync(0xffffffffu, s1, 2);
            s2 += __shfl_xor_sync(0xffffffffu, s2, 1);
            s2 += __shfl_xor_sync(0xffffffffu, s2, 2);
            if (tq == 0) {
                int e1 = t * 128 + w * 32 + mb * 16 + g;
                int e2 = e1 + 8;
                if (e1 < E) out[e1] = s1 + bias3;
                if (e2 < E) out[e2] = s2 + bias3;
            }
        }
        idxS = nS; idxD = nD;
        __syncwarp();   // fragment reads done before next tile's A stores
    }
}

// ---------------------------------------------------------------------------
extern "C" void kernel_launch(void* const* d_in, const int* in_sizes, int n_in,
                              void* d_out, int out_size) {
    const float* emb    = (const float*)d_in[0];
    const int*   eidx_w = (const int*)d_in[1];
    const float* W1     = (const float*)d_in[2];
    const float* b1     = (const float*)d_in[3];
    const float* W2     = (const float*)d_in[4];
    const float* b2     = (const float*)d_in[5];
    const float* W3     = (const float*)d_in[6];
    const float* b3     = (const float*)d_in[7];

    int N = in_sizes[0] / 128;
    int E = in_sizes[1] / 2;
    int nTilesP = (N + 127) / 128;
    int nTilesE = (E + 127) / 128;

    static int smem_set = 0;
    if (!smem_set) {
        cudaFuncSetAttribute(precompute_kernel,
                             cudaFuncAttributeMaxDynamicSharedMemorySize,
                             PRE_SMEM_BYTES);
        cudaFuncSetAttribute(edge_kernel,
                             cudaFuncAttributeMaxDynamicSharedMemorySize,
                             EDGE_SMEM_BYTES);
        smem_set = 1;
    }

    precompute_kernel<<<NSM, 256, PRE_SMEM_BYTES>>>(emb, W1, b1, N, nTilesP);
    edge_kernel<<<2 * NSM, 128, EDGE_SMEM_BYTES>>>(eidx_w, W2, b2, W3, b3,
                                                   (float*)d_out, E, N, nTilesE);
}

// round 12
// speedup vs baseline: 1.1604x; 1.1604x over previous
#include <cuda_runtime.h>
#include <cuda_bf16.h>
#include <cstdint>

// ---------------------------------------------------------------------------
// LinkWeightDecoder: out[e] = MLP(concat(emb[src_e], emb[dst_e]))
//   K1 (mma.sync bf16 hi/lo): P[n][0:256] = emb[n] @ [W1a|W1b] (+b1 on first half)
//   K2 (mma.sync bf16 hi/lo): 128-edge tiles; warp = (m-group, n-half):
//     32 edges x 32 outs per warp (acc=32 regs), B fragments amortized 2x.
//     Partial dot over each warp's 32 n-cols, combined via smem.
// ---------------------------------------------------------------------------

#define MAXN 100000
#define NSM  148

__device__ float g_P[MAXN * 256];   // per-node projections (102.4 MB)

// ---------------- helpers ----------------
__device__ __forceinline__ uint32_t smem_u32(const void* p) {
    uint32_t a;
    asm("{ .reg .u64 t; cvta.to.shared.u64 t, %1; cvt.u32.u64 %0, t; }"
        : "=r"(a) : "l"(p));
    return a;
}
#define SWZ(off) ((off) ^ (((off) >> 3) & 0x70))

__device__ __forceinline__ void ldsm4(uint32_t* r, uint32_t addr) {
    asm volatile("ldmatrix.sync.aligned.m8n8.x4.shared.b16 {%0,%1,%2,%3}, [%4];"
        : "=r"(r[0]), "=r"(r[1]), "=r"(r[2]), "=r"(r[3]) : "r"(addr));
}
__device__ __forceinline__ void ldsm4t(uint32_t* r, uint32_t addr) {
    asm volatile("ldmatrix.sync.aligned.m8n8.x4.trans.shared.b16 {%0,%1,%2,%3}, [%4];"
        : "=r"(r[0]), "=r"(r[1]), "=r"(r[2]), "=r"(r[3]) : "r"(addr));
}
__device__ __forceinline__ void mma16816(float* c, const uint32_t* a,
                                         uint32_t b0, uint32_t b1) {
    asm volatile(
        "mma.sync.aligned.m16n8k16.row.col.f32.bf16.bf16.f32 "
        "{%0,%1,%2,%3}, {%4,%5,%6,%7}, {%8,%9}, {%0,%1,%2,%3};"
        : "+f"(c[0]), "+f"(c[1]), "+f"(c[2]), "+f"(c[3])
        : "r"(a[0]), "r"(a[1]), "r"(a[2]), "r"(a[3]), "r"(b0), "r"(b1));
}
// split fp32 quad -> bf16 hi/lo packed uint2
__device__ __forceinline__ void split4(float4 h, uint2& uhi, uint2& ulo) {
    __nv_bfloat162 h01 = __float22bfloat162_rn(make_float2(h.x, h.y));
    __nv_bfloat162 h23 = __float22bfloat162_rn(make_float2(h.z, h.w));
    float2 f01 = __bfloat1622float2(h01);
    float2 f23 = __bfloat1622float2(h23);
    __nv_bfloat162 l01 = __float22bfloat162_rn(make_float2(h.x - f01.x, h.y - f01.y));
    __nv_bfloat162 l23 = __float22bfloat162_rn(make_float2(h.z - f23.x, h.w - f23.y));
    uhi.x = *(uint32_t*)&h01; uhi.y = *(uint32_t*)&h23;
    ulo.x = *(uint32_t*)&l01; ulo.y = *(uint32_t*)&l23;
}

// ---------------------------------------------------------------------------
// Kernel 1 (persistent, HMMA): P = emb @ [W1a|W1b] (+b1 fold on cols<128)
// (unchanged from passing rounds 9/10)
// ---------------------------------------------------------------------------
#define PA_HI 0
#define PA_LO 32768
#define PB_HI 65536
#define PB_LO 131072
#define PB1   196608
#define PRE_SMEM_BYTES (196608 + 1024)

__global__ __launch_bounds__(256, 1)
void precompute_kernel(const float* __restrict__ emb,
                       const float* __restrict__ W1,
                       const float* __restrict__ b1, int N, int nTiles) {
    extern __shared__ char smem[];
    const uint32_t sbase = smem_u32(smem);
    float* sB1 = (float*)(smem + PB1);

    const int tid  = threadIdx.x;
    const int lane = tid & 31, w = tid >> 5;

#pragma unroll 4
    for (int it = 0; it < 32; it++) {
        int idx = it * 256 + tid;
        int k = idx >> 6, og4 = (idx & 63) * 4;
        const float* sp = (og4 < 128) ? &W1[k * 128 + og4]
                                      : &W1[(k + 128) * 128 + (og4 - 128)];
        float4 v = *(const float4*)sp;
        uint2 uhi, ulo;
        split4(v, uhi, ulo);
        int c = og4 >> 6, o = og4 & 63;
        uint32_t off = c * 16384 + SWZ((uint32_t)(k * 128 + o * 2));
        *(uint2*)(smem + PB_HI + off) = uhi;
        *(uint2*)(smem + PB_LO + off) = ulo;
    }
    sB1[tid] = (tid < 128) ? b1[tid] : 0.f;
    __syncthreads();

    const int aRow  = w * 16 + (lane & 15);
    const int aHalf = (lane >> 4) * 16;
    const int bKrow = (lane & 7) + ((lane >> 3) & 1) * 8;
    const int bHalf = (lane >> 4) * 16;
    const int g = lane >> 2, tq = lane & 3;

    const float4* E4 = (const float4*)emb;
    const int grid = gridDim.x;

    for (int t = blockIdx.x; t < nTiles; t += grid) {
#pragma unroll 4
        for (int i = 0; i < 16; i++) {
            int row = w * 16 + i;
            int node = t * 128 + row; if (node >= N) node = N - 1;
            float4 v = __ldg(&E4[(long long)node * 32 + lane]);
            uint2 uhi, ulo;
            split4(v, uhi, ulo);
            int sub = lane >> 4;
            uint32_t boff = SWZ((uint32_t)(row * 128 + (lane & 15) * 8));
            char* pa = smem + sub * 16384 + boff;
            *(uint2*)(pa + PA_HI) = uhi;
            *(uint2*)(pa + PA_LO) = ulo;
        }
        __syncwarp();

#pragma unroll 1
        for (int c = 0; c < 4; c++) {
            const uint32_t bHi = sbase + PB_HI + c * 16384;
            const uint32_t bLo = sbase + PB_LO + c * 16384;

            uint32_t Ahi[8][4];
#pragma unroll
            for (int ks = 0; ks < 8; ks++) {
                uint32_t raw = (uint32_t)(aRow * 128 + (ks & 3) * 32 + aHalf);
                ldsm4(Ahi[ks], sbase + PA_HI + (ks >> 2) * 16384 + SWZ(raw));
            }

            float acc[8][4];
#pragma unroll
            for (int nf = 0; nf < 8; nf++)
#pragma unroll
                for (int p = 0; p < 4; p++) acc[nf][p] = 0.f;

#pragma unroll 2
            for (int ks = 0; ks < 8; ks++) {
                uint32_t Alo[4];
                uint32_t rawA = (uint32_t)(aRow * 128 + (ks & 3) * 32 + aHalf);
                ldsm4(Alo, sbase + PA_LO + (ks >> 2) * 16384 + SWZ(rawA));
#pragma unroll
                for (int nb = 0; nb < 4; nb++) {
                    uint32_t bfr[4];
                    uint32_t rawB = (uint32_t)((ks * 16 + bKrow) * 128 + nb * 32 + bHalf);
                    ldsm4t(bfr, bHi + SWZ(rawB));
                    mma16816(acc[2 * nb],     Ahi[ks], bfr[0], bfr[1]);
                    mma16816(acc[2 * nb + 1], Ahi[ks], bfr[2], bfr[3]);
                    mma16816(acc[2 * nb],     Alo,     bfr[0], bfr[1]);
                    mma16816(acc[2 * nb + 1], Alo,     bfr[2], bfr[3]);
                }
            }
#pragma unroll 2
            for (int ks = 0; ks < 8; ks++) {
#pragma unroll
                for (int nb = 0; nb < 4; nb++) {
                    uint32_t bfr[4];
                    uint32_t rawB = (uint32_t)((ks * 16 + bKrow) * 128 + nb * 32 + bHalf);
                    ldsm4t(bfr, bLo + SWZ(rawB));
                    mma16816(acc[2 * nb],     Ahi[ks], bfr[0], bfr[1]);
                    mma16816(acc[2 * nb + 1], Ahi[ks], bfr[2], bfr[3]);
                }
            }

            int n1 = t * 128 + w * 16 + g;
            int n2 = n1 + 8;
#pragma unroll
            for (int nf = 0; nf < 8; nf++) {
                int o = c * 64 + nf * 8 + tq * 2;
                float2 bias = *(const float2*)&sB1[o];
                if (n1 < N) {
                    float2 r = make_float2(acc[nf][0] + bias.x, acc[nf][1] + bias.y);
                    *(float2*)&g_P[(long long)n1 * 256 + o] = r;
                }
                if (n2 < N) {
                    float2 r = make_float2(acc[nf][2] + bias.x, acc[nf][3] + bias.y);
                    *(float2*)&g_P[(long long)n2 * 256 + o] = r;
                }
            }
        }
        __syncwarp();
    }
}

// ---------------------------------------------------------------------------
// Kernel 2: persistent HMMA, 128-edge tiles, 256 threads, 2 blocks/SM.
// Warp w = (m-group g=w&3, n-half nh=w>>2): 32 edges x 32 outs, acc=32 regs.
// Gather: warp w stages edges w*16..+15 (as round 10). 2 barriers/tile.
// ---------------------------------------------------------------------------
#define A_HI_OFF 0
#define A_LO_OFF 32768
#define B_HI_OFF 65536
#define B_LO_OFF 81920
#define SBW_OFF  98304
#define SPART_OFF 98816
#define EDGE_SMEM_BYTES (98816 + 1024 + 1024)

__global__ __launch_bounds__(256, 2)
void edge_kernel(const int* __restrict__ eidx_w,
                 const float* __restrict__ W2,
                 const float* __restrict__ b2,
                 const float* __restrict__ W3,
                 const float* __restrict__ b3,
                 float* __restrict__ out, int E, int N, int nTiles) {
    extern __shared__ char smem_raw[];
    char* sm = (char*)(((uintptr_t)smem_raw + 1023) & ~(uintptr_t)1023);
    const uint32_t sbase = smem_u32(sm);
    float4* sBW4 = (float4*)(sm + SBW_OFF);
    float*  sPart = (float*)(sm + SPART_OFF);
    __shared__ int sAny;

    const int tid  = threadIdx.x;
    const int lane = tid & 31, w = tid >> 5;
    const int g  = w & 3;        // m-group: edges g*32..+31
    const int nh = w >> 2;       // n-half: outs nh*32..+31

    // ---- one-time: dtype detect, W2 hi/lo staging, b2/W3 staging ----
    if (tid == 0) sAny = 0;
    __syncthreads();
    if (tid < 64 && eidx_w[2 * tid + 1] != 0) atomicOr(&sAny, 1);

#pragma unroll 4
    for (int it = 0; it < 32; it++) {
        int slot = it * 256 + tid;
        int k = slot >> 6, o = slot & 63;
        float wv = W2[k * 64 + o];
        __nv_bfloat16 hi = __float2bfloat16_rn(wv);
        __nv_bfloat16 lo = __float2bfloat16_rn(wv - __bfloat162float(hi));
        uint32_t off = SWZ((uint32_t)(k * 128 + o * 2));
        *(__nv_bfloat16*)(sm + B_HI_OFF + off) = hi;
        *(__nv_bfloat16*)(sm + B_LO_OFF + off) = lo;
    }
    if (tid < 32)
        sBW4[tid] = make_float4(b2[2 * tid], W3[2 * tid],
                                b2[2 * tid + 1], W3[2 * tid + 1]);
    __syncthreads();

    const int stride = sAny ? 1 : 2;
    const float bias3 = __ldg(&b3[0]);
    const char* Pb = (const char*)g_P;
    const int grid = gridDim.x;

    // ---- fragment geometry ----
    const int aHalf = (lane >> 4) * 16;
    const int bKrow = (lane & 7) + ((lane >> 3) & 1) * 8;
    const int bHalf = (lane >> 4) * 16;
    const int gq = lane >> 2, tq = lane & 3;

    // XOR-compressed bases.
    // A (m-group g): addr(ks) = (aBase0 + (ks>>2)*16384) ^ ((ks&3)<<5); mb1 = +2048
    const uint32_t Ra = (uint32_t)((g * 32 + (lane & 15)) * 128);
    const uint32_t aBase0 = sbase + A_HI_OFF + Ra
                          + ((uint32_t)aHalf ^ ((Ra >> 3) & 0x70));
    // B (n-half nh): addr(ks,nb) = (bBase0 + ks*2048) ^ (nb<<5); lo = +16384
    const uint32_t Rb = (uint32_t)(bKrow * 128);
    const uint32_t bBase0 = sbase + B_HI_OFF + Rb
                          + ((uint32_t)(nh * 64 + bHalf) ^ ((Rb >> 3) & 0x70));

    // index loader (gather role: warp w stages edges t*128 + w*16 .. +15)
    auto load_idx = [&](int t) -> int {
        int l = lane & 15;
        int e = t * 128 + w * 16 + l; if (e >= E) e = E - 1;
        long long off = (lane < 16) ? (long long)e * stride
                                    : ((long long)E + e) * stride;
        int v = eidx_w[off];
        return min(max(v, 0), N - 1);
    };

    int t = blockIdx.x;
    int myidx = (t < nTiles) ? load_idx(t) : 0;

    for (; t < nTiles; t += grid) {
        // ---- gather + relu + bf16 hi/lo -> 16 staged A rows per warp ----
#pragma unroll 4
        for (int i = 0; i < 16; i++) {
            int si = __shfl_sync(0xffffffffu, myidx, i);
            int di = __shfl_sync(0xffffffffu, myidx, 16 + i);
            float4 a = __ldg((const float4*)(Pb + (uint32_t)si * 1024u
                                                + (uint32_t)(lane * 16)));
            float4 b = __ldg((const float4*)(Pb + (uint32_t)di * 1024u + 512u
                                                + (uint32_t)(lane * 16)));
            float4 h;
            h.x = fmaxf(a.x + b.x, 0.f);
            h.y = fmaxf(a.y + b.y, 0.f);
            h.z = fmaxf(a.z + b.z, 0.f);
            h.w = fmaxf(a.w + b.w, 0.f);
            uint2 uhi, ulo;
            split4(h, uhi, ulo);

            int row = w * 16 + i;
            int sub = lane >> 4;
            uint32_t boff = SWZ((uint32_t)(row * 128 + (lane & 15) * 8));
            char* pa = sm + sub * 16384 + boff;
            *(uint2*)(pa + A_HI_OFF) = uhi;
            *(uint2*)(pa + A_LO_OFF) = ulo;
        }
        __syncthreads();   // B1: all A rows visible (cross-warp reads follow)

        // ---- prefetch next tile's indices (hidden under MMA) ----
        int tn = t + grid;
        int nextidx = (tn < nTiles) ? load_idx(tn) : 0;

        // ---- fused 3-pass GEMM: M=32 (2 m-blocks), N=32 (this n-half) ----
        float acc[2][4][4];
#pragma unroll
        for (int mb = 0; mb < 2; mb++)
#pragma unroll
            for (int nf = 0; nf < 4; nf++)
#pragma unroll
                for (int p = 0; p < 4; p++) acc[mb][nf][p] = 0.f;

#pragma unroll
        for (int ks = 0; ks < 8; ks++) {
            uint32_t aH0[4], aH1[4], aL0[4], aL1[4];
            uint32_t aA = (aBase0 + ((ks >> 2) * 16384)) ^ ((ks & 3) << 5);
            ldsm4(aH0, aA);
            ldsm4(aH1, aA + 2048);
            ldsm4(aL0, aA + 32768);
            ldsm4(aL1, aA + 32768 + 2048);
            uint32_t bRow = bBase0 + (uint32_t)(ks * 2048);
#pragma unroll
            for (int nb = 0; nb < 2; nb++) {
                uint32_t bh[4], bl[4];
                uint32_t bA = bRow ^ (nb << 5);
                ldsm4t(bh, bA);
                ldsm4t(bl, bA + 16384);
                mma16816(acc[0][2 * nb],     aH0, bh[0], bh[1]);
                mma16816(acc[0][2 * nb + 1], aH0, bh[2], bh[3]);
                mma16816(acc[1][2 * nb],     aH1, bh[0], bh[1]);
                mma16816(acc[1][2 * nb + 1], aH1, bh[2], bh[3]);
                mma16816(acc[0][2 * nb],     aL0, bh[0], bh[1]);
                mma16816(acc[0][2 * nb + 1], aL0, bh[2], bh[3]);
                mma16816(acc[1][2 * nb],     aL1, bh[0], bh[1]);
                mma16816(acc[1][2 * nb + 1], aL1, bh[2], bh[3]);
                mma16816(acc[0][2 * nb],     aH0, bl[0], bl[1]);
                mma16816(acc[0][2 * nb + 1], aH0, bl[2], bl[3]);
                mma16816(acc[1][2 * nb],     aH1, bl[0], bl[1]);
                mma16816(acc[1][2 * nb + 1], aH1, bl[2], bl[3]);
            }
        }

        // ---- partial epilogue: relu(D+b2)*W3 over this warp's 32 n-cols ----
#pragma unroll
        for (int mb = 0; mb < 2; mb++) {
            float s1 = 0.f, s2 = 0.f;
#pragma unroll
            for (int nf = 0; nf < 4; nf++) {
                float4 bw = sBW4[nh * 16 + nf * 4 + tq];
                s1 += fmaxf(acc[mb][nf][0] + bw.x, 0.f) * bw.y
                    + fmaxf(acc[mb][nf][1] + bw.z, 0.f) * bw.w;
                s2 += fmaxf(acc[mb][nf][2] + bw.x, 0.f) * bw.y
                    + fmaxf(acc[mb][nf][3] + bw.z, 0.f) * bw.w;
            }
            s1 += __shfl_xor_sync(0xffffffffu, s1, 1);
            s1 += __shfl_xor_sync(0xffffffffu, s1, 2);
            s2 += __shfl_xor_sync(0xffffffffu, s2, 1);
            s2 += __shfl_xor_sync(0xffffffffu, s2, 2);
            if (tq == 0) {
                int le = g * 32 + mb * 16 + gq;
                sPart[nh * 128 + le] = s1;
                sPart[nh * 128 + le + 8] = s2;
            }
        }
        __syncthreads();   // B2: partials visible

        // ---- combine n-halves + store ----
        if (tid < 128) {
            int e = t * 128 + tid;
            if (e < E) out[e] = sPart[tid] + sPart[128 + tid] + bias3;
        }
        myidx = nextidx;
        // next tile's B1 orders combine reads vs next partial writes;
        // A-region overwrite (gather) is disjoint from sPart.
    }
}

// ---------------------------------------------------------------------------
extern "C" void kernel_launch(void* const* d_in, const int* in_sizes, int n_in,
                              void* d_out, int out_size) {
    const float* emb    = (const float*)d_in[0];
    const int*   eidx_w = (const int*)d_in[1];
    const float* W1     = (const float*)d_in[2];
    const float* b1     = (const float*)d_in[3];
    const float* W2     = (const float*)d_in[4];
    const float* b2     = (const float*)d_in[5];
    const float* W3     = (const float*)d_in[6];
    const float* b3     = (const float*)d_in[7];

    int N = in_sizes[0] / 128;
    int E = in_sizes[1] / 2;
    int nTilesP = (N + 127) / 128;
    int nTilesE = (E + 127) / 128;

    static int smem_set = 0;
    if (!smem_set) {
        cudaFuncSetAttribute(precompute_kernel,
                             cudaFuncAttributeMaxDynamicSharedMemorySize,
                             PRE_SMEM_BYTES);
        cudaFuncSetAttribute(edge_kernel,
                             cudaFuncAttributeMaxDynamicSharedMemorySize,
                             EDGE_SMEM_BYTES);
        smem_set = 1;
    }

    precompute_kernel<<<NSM, 256, PRE_SMEM_BYTES>>>(emb, W1, b1, N, nTilesP);
    edge_kernel<<<2 * NSM, 256, EDGE_SMEM_BYTES>>>(eidx_w, W2, b2, W3, b3,
                                                   (float*)d_out, E, N, nTilesE);
}

// round 13
// speedup vs baseline: 1.4075x; 1.2130x over previous
#include <cuda_runtime.h>
#include <cuda_bf16.h>
#include <cstdint>

// ---------------------------------------------------------------------------
// LinkWeightDecoder: out[e] = MLP(concat(emb[src_e], emb[dst_e]))
//   K1 (HMMA bf16 hi/lo): P[n][0:256] = emb[n] @ [W1a|W1b] (+b1 on first half)
//      fused 3-pass loop, XOR addresses, A fragments hoisted across n-chunks.
//   K2 (HMMA bf16 hi/lo): round-10 design: 128-edge tiles, 8 independent
//      warps x 16 edges, fused 3-pass GEMM, XOR-compressed addresses.
// ---------------------------------------------------------------------------

#define MAXN 100000
#define NSM  148

__device__ float g_P[MAXN * 256];   // per-node projections (102.4 MB)

// ---------------- helpers ----------------
__device__ __forceinline__ uint32_t smem_u32(const void* p) {
    uint32_t a;
    asm("{ .reg .u64 t; cvta.to.shared.u64 t, %1; cvt.u32.u64 %0, t; }"
        : "=r"(a) : "l"(p));
    return a;
}
#define SWZ(off) ((off) ^ (((off) >> 3) & 0x70))

__device__ __forceinline__ void ldsm4(uint32_t* r, uint32_t addr) {
    asm volatile("ldmatrix.sync.aligned.m8n8.x4.shared.b16 {%0,%1,%2,%3}, [%4];"
        : "=r"(r[0]), "=r"(r[1]), "=r"(r[2]), "=r"(r[3]) : "r"(addr));
}
__device__ __forceinline__ void ldsm4t(uint32_t* r, uint32_t addr) {
    asm volatile("ldmatrix.sync.aligned.m8n8.x4.trans.shared.b16 {%0,%1,%2,%3}, [%4];"
        : "=r"(r[0]), "=r"(r[1]), "=r"(r[2]), "=r"(r[3]) : "r"(addr));
}
__device__ __forceinline__ void mma16816(float* c, const uint32_t* a,
                                         uint32_t b0, uint32_t b1) {
    asm volatile(
        "mma.sync.aligned.m16n8k16.row.col.f32.bf16.bf16.f32 "
        "{%0,%1,%2,%3}, {%4,%5,%6,%7}, {%8,%9}, {%0,%1,%2,%3};"
        : "+f"(c[0]), "+f"(c[1]), "+f"(c[2]), "+f"(c[3])
        : "r"(a[0]), "r"(a[1]), "r"(a[2]), "r"(a[3]), "r"(b0), "r"(b1));
}
// split fp32 quad -> bf16 hi/lo packed uint2
__device__ __forceinline__ void split4(float4 h, uint2& uhi, uint2& ulo) {
    __nv_bfloat162 h01 = __float22bfloat162_rn(make_float2(h.x, h.y));
    __nv_bfloat162 h23 = __float22bfloat162_rn(make_float2(h.z, h.w));
    float2 f01 = __bfloat1622float2(h01);
    float2 f23 = __bfloat1622float2(h23);
    __nv_bfloat162 l01 = __float22bfloat162_rn(make_float2(h.x - f01.x, h.y - f01.y));
    __nv_bfloat162 l23 = __float22bfloat162_rn(make_float2(h.z - f23.x, h.w - f23.y));
    uhi.x = *(uint32_t*)&h01; uhi.y = *(uint32_t*)&h23;
    ulo.x = *(uint32_t*)&l01; ulo.y = *(uint32_t*)&l23;
}

// ---------------------------------------------------------------------------
// Kernel 1 (persistent, HMMA): P = emb @ [W1a|W1b] (+b1 fold on cols<128)
// 128-node tiles, 8 independent warps x 16 rows. Fused 3-pass, XOR addrs,
// A fragments (hi+lo, 64 regs) hoisted across the 4 n-chunks.
// ---------------------------------------------------------------------------
#define PA_HI 0
#define PA_LO 32768
#define PB_HI 65536
#define PB_LO 131072
#define PB1   196608
#define PRE_SMEM_BYTES (196608 + 1024 + 1024)

__global__ __launch_bounds__(256, 1)
void precompute_kernel(const float* __restrict__ emb,
                       const float* __restrict__ W1,
                       const float* __restrict__ b1, int N, int nTiles) {
    extern __shared__ char smem_raw[];
    char* sm = (char*)(((uintptr_t)smem_raw + 1023) & ~(uintptr_t)1023);
    const uint32_t sbase = smem_u32(sm);
    float* sB1 = (float*)(sm + PB1);

    const int tid  = threadIdx.x;
    const int lane = tid & 31, w = tid >> 5;

    // ---- one-time: stage W1eff hi/lo (4 chunk-tiles of [128k x 64n]) ----
#pragma unroll 4
    for (int it = 0; it < 32; it++) {
        int idx = it * 256 + tid;
        int k = idx >> 6, og4 = (idx & 63) * 4;
        const float* sp = (og4 < 128) ? &W1[k * 128 + og4]
                                      : &W1[(k + 128) * 128 + (og4 - 128)];
        float4 v = *(const float4*)sp;
        uint2 uhi, ulo;
        split4(v, uhi, ulo);
        int c = og4 >> 6, o = og4 & 63;
        uint32_t off = c * 16384 + SWZ((uint32_t)(k * 128 + o * 2));
        *(uint2*)(sm + PB_HI + off) = uhi;
        *(uint2*)(sm + PB_LO + off) = ulo;
    }
    sB1[tid] = (tid < 128) ? b1[tid] : 0.f;
    __syncthreads();

    // ---- fragment geometry + XOR-compressed bases ----
    const int aHalf = (lane >> 4) * 16;
    const int bKrow = (lane & 7) + ((lane >> 3) & 1) * 8;
    const int bHalf = (lane >> 4) * 16;
    const int g = lane >> 2, tq = lane & 3;

    const uint32_t Ra = (uint32_t)((w * 16 + (lane & 15)) * 128);
    const uint32_t aBase0 = sbase + PA_HI + Ra
                          + ((uint32_t)aHalf ^ ((Ra >> 3) & 0x70));
    const uint32_t Rb = (uint32_t)(bKrow * 128);
    const uint32_t bBaseC = sbase + PB_HI + Rb
                          + ((uint32_t)bHalf ^ ((Rb >> 3) & 0x70));

    const float4* E4 = (const float4*)emb;
    const int grid = gridDim.x;

    for (int t = blockIdx.x; t < nTiles; t += grid) {
        // ---- stage own 16 rows (emb fp32 -> bf16 hi/lo) ----
#pragma unroll 4
        for (int i = 0; i < 16; i++) {
            int row = w * 16 + i;
            int node = t * 128 + row; if (node >= N) node = N - 1;
            float4 v = __ldg(&E4[(long long)node * 32 + lane]);
            uint2 uhi, ulo;
            split4(v, uhi, ulo);
            int sub = lane >> 4;
            uint32_t boff = SWZ((uint32_t)(row * 128 + (lane & 15) * 8));
            char* pa = sm + sub * 16384 + boff;
            *(uint2*)(pa + PA_HI) = uhi;
            *(uint2*)(pa + PA_LO) = ulo;
        }
        __syncwarp();

        // ---- hoist A fragments once per tile (chunk-invariant) ----
        uint32_t Ahi[8][4], Alo[8][4];
#pragma unroll
        for (int ks = 0; ks < 8; ks++) {
            uint32_t aA = (aBase0 + ((ks >> 2) * 16384)) ^ ((ks & 3) << 5);
            ldsm4(Ahi[ks], aA);
            ldsm4(Alo[ks], aA + 32768);
        }

        // ---- 4 n-chunks of 64 cols, fused 3-pass GEMM each ----
        const int n1 = t * 128 + w * 16 + g;
        const int n2 = n1 + 8;
#pragma unroll 1
        for (int c = 0; c < 4; c++) {
            const uint32_t bBase0 = bBaseC + (uint32_t)(c * 16384);

            float acc[8][4];
#pragma unroll
            for (int nf = 0; nf < 8; nf++)
#pragma unroll
                for (int p = 0; p < 4; p++) acc[nf][p] = 0.f;

#pragma unroll
            for (int ks = 0; ks < 8; ks++) {
                uint32_t bRow = bBase0 + (uint32_t)(ks * 2048);
#pragma unroll
                for (int nb = 0; nb < 4; nb++) {
                    uint32_t bh[4], bl[4];
                    uint32_t bA = bRow ^ (nb << 5);
                    ldsm4t(bh, bA);
                    ldsm4t(bl, bA + 65536);
                    mma16816(acc[2 * nb],     Ahi[ks], bh[0], bh[1]);
                    mma16816(acc[2 * nb + 1], Ahi[ks], bh[2], bh[3]);
                    mma16816(acc[2 * nb],     Alo[ks], bh[0], bh[1]);
                    mma16816(acc[2 * nb + 1], Alo[ks], bh[2], bh[3]);
                    mma16816(acc[2 * nb],     Ahi[ks], bl[0], bl[1]);
                    mma16816(acc[2 * nb + 1], Ahi[ks], bl[2], bl[3]);
                }
            }

            // ---- epilogue: +b1 (cols<128), store fp32 pairs to g_P ----
#pragma unroll
            for (int nf = 0; nf < 8; nf++) {
                int o = c * 64 + nf * 8 + tq * 2;
                float2 bias = *(const float2*)&sB1[o];
                if (n1 < N) {
                    float2 r = make_float2(acc[nf][0] + bias.x, acc[nf][1] + bias.y);
                    *(float2*)&g_P[(long long)n1 * 256 + o] = r;
                }
                if (n2 < N) {
                    float2 r = make_float2(acc[nf][2] + bias.x, acc[nf][3] + bias.y);
                    *(float2*)&g_P[(long long)n2 * 256 + o] = r;
                }
            }
        }
        __syncwarp();   // own A-tile reads done before next tile's stores
    }
}

// ---------------------------------------------------------------------------
// Kernel 2: round-10 winner. Persistent HMMA, 128-edge tiles, 8 independent
// warps x 16 edges, 256 thr, 2 blocks/SM. Fused 3-pass, XOR addresses
// (bBase0 + ks*2048 compression), 32-bit gather offsets.
// ---------------------------------------------------------------------------
#define A_HI_OFF 0
#define A_LO_OFF 32768
#define B_HI_OFF 65536
#define B_LO_OFF 81920
#define SBW_OFF  98304
#define EDGE_SMEM_BYTES (98304 + 512 + 1024)

__global__ __launch_bounds__(256, 2)
void edge_kernel(const int* __restrict__ eidx_w,
                 const float* __restrict__ W2,
                 const float* __restrict__ b2,
                 const float* __restrict__ W3,
                 const float* __restrict__ b3,
                 float* __restrict__ out, int E, int N, int nTiles) {
    extern __shared__ char smem_raw[];
    char* sm = (char*)(((uintptr_t)smem_raw + 1023) & ~(uintptr_t)1023);
    const uint32_t sbase = smem_u32(sm);
    float4* sBW4 = (float4*)(sm + SBW_OFF);
    __shared__ int sAny;

    const int tid  = threadIdx.x;
    const int lane = tid & 31, w = tid >> 5;

    // ---- one-time: dtype detect, W2 hi/lo staging, b2/W3 staging ----
    if (tid == 0) sAny = 0;
    __syncthreads();
    if (tid < 64 && eidx_w[2 * tid + 1] != 0) atomicOr(&sAny, 1);

#pragma unroll 4
    for (int it = 0; it < 32; it++) {
        int slot = it * 256 + tid;
        int k = slot >> 6, o = slot & 63;
        float wv = W2[k * 64 + o];
        __nv_bfloat16 hi = __float2bfloat16_rn(wv);
        __nv_bfloat16 lo = __float2bfloat16_rn(wv - __bfloat162float(hi));
        uint32_t off = SWZ((uint32_t)(k * 128 + o * 2));
        *(__nv_bfloat16*)(sm + B_HI_OFF + off) = hi;
        *(__nv_bfloat16*)(sm + B_LO_OFF + off) = lo;
    }
    if (tid < 32)
        sBW4[tid] = make_float4(b2[2 * tid], W3[2 * tid],
                                b2[2 * tid + 1], W3[2 * tid + 1]);
    __syncthreads();

    const int stride = sAny ? 1 : 2;
    const float bias3 = __ldg(&b3[0]);
    const char* Pb = (const char*)g_P;
    const int grid = gridDim.x;

    // ---- fragment geometry + XOR-compressed bases ----
    const int aHalf = (lane >> 4) * 16;
    const int bKrow = (lane & 7) + ((lane >> 3) & 1) * 8;
    const int bHalf = (lane >> 4) * 16;
    const int g = lane >> 2, tq = lane & 3;

    const uint32_t Ra = (uint32_t)((w * 16 + (lane & 15)) * 128);
    const uint32_t aBase0 = sbase + A_HI_OFF + Ra
                          + ((uint32_t)aHalf ^ ((Ra >> 3) & 0x70));
    const uint32_t Rb = (uint32_t)(bKrow * 128);
    const uint32_t bBase0 = sbase + B_HI_OFF + Rb
                          + ((uint32_t)bHalf ^ ((Rb >> 3) & 0x70));

    // index loader (warp w owns edges t*128 + w*16 .. +15)
    auto load_idx = [&](int t) -> int {
        int l = lane & 15;
        int e = t * 128 + w * 16 + l; if (e >= E) e = E - 1;
        long long off = (lane < 16) ? (long long)e * stride
                                    : ((long long)E + e) * stride;
        int v = eidx_w[off];
        return min(max(v, 0), N - 1);
    };

    int t = blockIdx.x;
    int myidx = (t < nTiles) ? load_idx(t) : 0;

    for (; t < nTiles; t += grid) {
        // ---- gather + relu + bf16 hi/lo -> own 16 A rows ----
#pragma unroll 4
        for (int i = 0; i < 16; i++) {
            int si = __shfl_sync(0xffffffffu, myidx, i);
            int di = __shfl_sync(0xffffffffu, myidx, 16 + i);
            float4 a = __ldg((const float4*)(Pb + (uint32_t)si * 1024u
                                                + (uint32_t)(lane * 16)));
            float4 b = __ldg((const float4*)(Pb + (uint32_t)di * 1024u + 512u
                                                + (uint32_t)(lane * 16)));
            float4 h;
            h.x = fmaxf(a.x + b.x, 0.f);
            h.y = fmaxf(a.y + b.y, 0.f);
            h.z = fmaxf(a.z + b.z, 0.f);
            h.w = fmaxf(a.w + b.w, 0.f);
            uint2 uhi, ulo;
            split4(h, uhi, ulo);

            int row = w * 16 + i;
            int sub = lane >> 4;
            uint32_t boff = SWZ((uint32_t)(row * 128 + (lane & 15) * 8));
            char* pa = sm + sub * 16384 + boff;
            *(uint2*)(pa + A_HI_OFF) = uhi;
            *(uint2*)(pa + A_LO_OFF) = ulo;
        }
        __syncwarp();

        // ---- prefetch next tile's indices (hidden under MMA) ----
        int tn = t + grid;
        int nextidx = (tn < nTiles) ? load_idx(tn) : 0;

        // ---- fused 3-pass GEMM: Ahi·Bhi + Alo·Bhi + Ahi·Blo ----
        float acc[8][4];
#pragma unroll
        for (int nf = 0; nf < 8; nf++)
#pragma unroll
            for (int p = 0; p < 4; p++) acc[nf][p] = 0.f;

#pragma unroll
        for (int ks = 0; ks < 8; ks++) {
            uint32_t a_hi[4], a_lo[4];
            uint32_t aA = (aBase0 + ((ks >> 2) * 16384)) ^ ((ks & 3) << 5);
            ldsm4(a_hi, aA);
            ldsm4(a_lo, aA + 32768);
            uint32_t bRow = bBase0 + (uint32_t)(ks * 2048);
#pragma unroll
            for (int nb = 0; nb < 4; nb++) {
                uint32_t bh[4], bl[4];
                uint32_t bA = bRow ^ (nb << 5);
                ldsm4t(bh, bA);
                ldsm4t(bl, bA + 16384);
                mma16816(acc[2 * nb],     a_hi, bh[0], bh[1]);
                mma16816(acc[2 * nb + 1], a_hi, bh[2], bh[3]);
                mma16816(acc[2 * nb],     a_lo, bh[0], bh[1]);
                mma16816(acc[2 * nb + 1], a_lo, bh[2], bh[3]);
                mma16816(acc[2 * nb],     a_hi, bl[0], bl[1]);
                mma16816(acc[2 * nb + 1], a_hi, bl[2], bl[3]);
            }
        }

        // ---- epilogue: +b2, relu, dot W3, 4-lane reduce, store ----
        float s1 = 0.f, s2 = 0.f;
#pragma unroll
        for (int nf = 0; nf < 8; nf++) {
            float4 bw = sBW4[nf * 4 + tq];
            s1 += fmaxf(acc[nf][0] + bw.x, 0.f) * bw.y
                + fmaxf(acc[nf][1] + bw.z, 0.f) * bw.w;
            s2 += fmaxf(acc[nf][2] + bw.x, 0.f) * bw.y
                + fmaxf(acc[nf][3] + bw.z, 0.f) * bw.w;
        }
        s1 += __shfl_xor_sync(0xffffffffu, s1, 1);
        s1 += __shfl_xor_sync(0xffffffffu, s1, 2);
        s2 += __shfl_xor_sync(0xffffffffu, s2, 1);
        s2 += __shfl_xor_sync(0xffffffffu, s2, 2);
        if (tq == 0) {
            int e1 = t * 128 + w * 16 + g;
            int e2 = e1 + 8;
            if (e1 < E) out[e1] = s1 + bias3;
            if (e2 < E) out[e2] = s2 + bias3;
        }
        myidx = nextidx;
        __syncwarp();   // fragment reads done before next tile's A stores
    }
}

// ---------------------------------------------------------------------------
extern "C" void kernel_launch(void* const* d_in, const int* in_sizes, int n_in,
                              void* d_out, int out_size) {
    const float* emb    = (const float*)d_in[0];
    const int*   eidx_w = (const int*)d_in[1];
    const float* W1     = (const float*)d_in[2];
    const float* b1     = (const float*)d_in[3];
    const float* W2     = (const float*)d_in[4];
    const float* b2     = (const float*)d_in[5];
    const float* W3     = (const float*)d_in[6];
    const float* b3     = (const float*)d_in[7];

    int N = in_sizes[0] / 128;
    int E = in_sizes[1] / 2;
    int nTilesP = (N + 127) / 128;
    int nTilesE = (E + 127) / 128;

    static int smem_set = 0;
    if (!smem_set) {
        cudaFuncSetAttribute(precompute_kernel,
                             cudaFuncAttributeMaxDynamicSharedMemorySize,
                             PRE_SMEM_BYTES);
        cudaFuncSetAttribute(edge_kernel,
                             cudaFuncAttributeMaxDynamicSharedMemorySize,
                             EDGE_SMEM_BYTES);
        smem_set = 1;
    }

    precompute_kernel<<<NSM, 256, PRE_SMEM_BYTES>>>(emb, W1, b1, N, nTilesP);
    edge_kernel<<<2 * NSM, 256, EDGE_SMEM_BYTES>>>(eidx_w, W2, b2, W3, b3,
                                                   (float*)d_out, E, N, nTilesE);
}

// round 14
// speedup vs baseline: 1.6908x; 1.2012x over previous
#include <cuda_runtime.h>
#include <cuda_fp16.h>
#include <cstdint>

// ---------------------------------------------------------------------------
// LinkWeightDecoder: out[e] = MLP(concat(emb[src_e], emb[dst_e]))
//   fp16 2-pass HMMA: A split hi/lo (fp16, 22-bit effective), B single fp16.
//   D = Ah·Bh + Al·Bh  (B rounding error ~2^-11 stat ~1e-4 << 1e-3 tol).
//   K1: P[n][0:256] = emb[n] @ [W1a|W1b] (+b1 on first half)
//   K2: 128-edge tiles, 8 independent warps x 16 edges, XOR-compressed addrs.
// ---------------------------------------------------------------------------

#define MAXN 100000
#define NSM  148

__device__ float g_P[MAXN * 256];   // per-node projections (102.4 MB)

// ---------------- helpers ----------------
__device__ __forceinline__ uint32_t smem_u32(const void* p) {
    uint32_t a;
    asm("{ .reg .u64 t; cvta.to.shared.u64 t, %1; cvt.u32.u64 %0, t; }"
        : "=r"(a) : "l"(p));
    return a;
}
#define SWZ(off) ((off) ^ (((off) >> 3) & 0x70))

__device__ __forceinline__ void ldsm4(uint32_t* r, uint32_t addr) {
    asm volatile("ldmatrix.sync.aligned.m8n8.x4.shared.b16 {%0,%1,%2,%3}, [%4];"
        : "=r"(r[0]), "=r"(r[1]), "=r"(r[2]), "=r"(r[3]) : "r"(addr));
}
__device__ __forceinline__ void ldsm4t(uint32_t* r, uint32_t addr) {
    asm volatile("ldmatrix.sync.aligned.m8n8.x4.trans.shared.b16 {%0,%1,%2,%3}, [%4];"
        : "=r"(r[0]), "=r"(r[1]), "=r"(r[2]), "=r"(r[3]) : "r"(addr));
}
__device__ __forceinline__ void mma16816(float* c, const uint32_t* a,
                                         uint32_t b0, uint32_t b1) {
    asm volatile(
        "mma.sync.aligned.m16n8k16.row.col.f32.f16.f16.f32 "
        "{%0,%1,%2,%3}, {%4,%5,%6,%7}, {%8,%9}, {%0,%1,%2,%3};"
        : "+f"(c[0]), "+f"(c[1]), "+f"(c[2]), "+f"(c[3])
        : "r"(a[0]), "r"(a[1]), "r"(a[2]), "r"(a[3]), "r"(b0), "r"(b1));
}
// split fp32 quad -> fp16 hi/lo packed uint2
__device__ __forceinline__ void split4(float4 h, uint2& uhi, uint2& ulo) {
    __half2 h01 = __float22half2_rn(make_float2(h.x, h.y));
    __half2 h23 = __float22half2_rn(make_float2(h.z, h.w));
    float2 f01 = __half22float2(h01);
    float2 f23 = __half22float2(h23);
    __half2 l01 = __float22half2_rn(make_float2(h.x - f01.x, h.y - f01.y));
    __half2 l23 = __float22half2_rn(make_float2(h.z - f23.x, h.w - f23.y));
    uhi.x = *(uint32_t*)&h01; uhi.y = *(uint32_t*)&h23;
    ulo.x = *(uint32_t*)&l01; ulo.y = *(uint32_t*)&l23;
}
// round fp32 quad -> single fp16 packed uint2
__device__ __forceinline__ uint2 pack4h(float4 v) {
    __half2 p01 = __float22half2_rn(make_float2(v.x, v.y));
    __half2 p23 = __float22half2_rn(make_float2(v.z, v.w));
    uint2 u;
    u.x = *(uint32_t*)&p01; u.y = *(uint32_t*)&p23;
    return u;
}

// ---------------------------------------------------------------------------
// Kernel 1 (persistent, HMMA fp16 2-pass): P = emb @ [W1a|W1b] (+b1 fold)
// 128-node tiles, 8 independent warps x 16 rows. A frags hoisted per tile.
// ---------------------------------------------------------------------------
#define PA_HI 0
#define PA_LO 32768
#define PB_HI 65536
#define PB1   131072
#define PRE_SMEM_BYTES (131072 + 1024 + 1024)

__global__ __launch_bounds__(256, 1)
void precompute_kernel(const float* __restrict__ emb,
                       const float* __restrict__ W1,
                       const float* __restrict__ b1, int N, int nTiles) {
    extern __shared__ char smem_raw[];
    char* sm = (char*)(((uintptr_t)smem_raw + 1023) & ~(uintptr_t)1023);
    const uint32_t sbase = smem_u32(sm);
    float* sB1 = (float*)(sm + PB1);

    const int tid  = threadIdx.x;
    const int lane = tid & 31, w = tid >> 5;

    // ---- one-time: stage W1eff fp16 (4 chunk-tiles of [128k x 64n]) ----
#pragma unroll 4
    for (int it = 0; it < 32; it++) {
        int idx = it * 256 + tid;
        int k = idx >> 6, og4 = (idx & 63) * 4;
        const float* sp = (og4 < 128) ? &W1[k * 128 + og4]
                                      : &W1[(k + 128) * 128 + (og4 - 128)];
        float4 v = *(const float4*)sp;
        int c = og4 >> 6, o = og4 & 63;
        uint32_t off = c * 16384 + SWZ((uint32_t)(k * 128 + o * 2));
        *(uint2*)(sm + PB_HI + off) = pack4h(v);
    }
    sB1[tid] = (tid < 128) ? b1[tid] : 0.f;
    __syncthreads();

    // ---- fragment geometry + XOR-compressed bases ----
    const int aHalf = (lane >> 4) * 16;
    const int bKrow = (lane & 7) + ((lane >> 3) & 1) * 8;
    const int bHalf = (lane >> 4) * 16;
    const int g = lane >> 2, tq = lane & 3;

    const uint32_t Ra = (uint32_t)((w * 16 + (lane & 15)) * 128);
    const uint32_t aBase0 = sbase + PA_HI + Ra
                          + ((uint32_t)aHalf ^ ((Ra >> 3) & 0x70));
    const uint32_t Rb = (uint32_t)(bKrow * 128);
    const uint32_t bBaseC = sbase + PB_HI + Rb
                          + ((uint32_t)bHalf ^ ((Rb >> 3) & 0x70));

    const float4* E4 = (const float4*)emb;
    const int grid = gridDim.x;

    for (int t = blockIdx.x; t < nTiles; t += grid) {
        // ---- stage own 16 rows (emb fp32 -> fp16 hi/lo) ----
#pragma unroll 4
        for (int i = 0; i < 16; i++) {
            int row = w * 16 + i;
            int node = t * 128 + row; if (node >= N) node = N - 1;
            float4 v = __ldg(&E4[(long long)node * 32 + lane]);
            uint2 uhi, ulo;
            split4(v, uhi, ulo);
            int sub = lane >> 4;
            uint32_t boff = SWZ((uint32_t)(row * 128 + (lane & 15) * 8));
            char* pa = sm + sub * 16384 + boff;
            *(uint2*)(pa + PA_HI) = uhi;
            *(uint2*)(pa + PA_LO) = ulo;
        }
        __syncwarp();

        // ---- hoist A fragments once per tile (chunk-invariant) ----
        uint32_t Ahi[8][4], Alo[8][4];
#pragma unroll
        for (int ks = 0; ks < 8; ks++) {
            uint32_t aA = (aBase0 + ((ks >> 2) * 16384)) ^ ((ks & 3) << 5);
            ldsm4(Ahi[ks], aA);
            ldsm4(Alo[ks], aA + 32768);
        }

        // ---- 4 n-chunks of 64 cols, fp16 2-pass GEMM each ----
        const int n1 = t * 128 + w * 16 + g;
        const int n2 = n1 + 8;
#pragma unroll 1
        for (int c = 0; c < 4; c++) {
            const uint32_t bBase0 = bBaseC + (uint32_t)(c * 16384);

            float acc[8][4];
#pragma unroll
            for (int nf = 0; nf < 8; nf++)
#pragma unroll
                for (int p = 0; p < 4; p++) acc[nf][p] = 0.f;

#pragma unroll
            for (int ks = 0; ks < 8; ks++) {
                uint32_t bRow = bBase0 + (uint32_t)(ks * 2048);
#pragma unroll
                for (int nb = 0; nb < 4; nb++) {
                    uint32_t bh[4];
                    ldsm4t(bh, bRow ^ (nb << 5));
                    mma16816(acc[2 * nb],     Ahi[ks], bh[0], bh[1]);
                    mma16816(acc[2 * nb + 1], Ahi[ks], bh[2], bh[3]);
                    mma16816(acc[2 * nb],     Alo[ks], bh[0], bh[1]);
                    mma16816(acc[2 * nb + 1], Alo[ks], bh[2], bh[3]);
                }
            }

            // ---- epilogue: +b1 (cols<128), store fp32 pairs to g_P ----
#pragma unroll
            for (int nf = 0; nf < 8; nf++) {
                int o = c * 64 + nf * 8 + tq * 2;
                float2 bias = *(const float2*)&sB1[o];
                if (n1 < N) {
                    float2 r = make_float2(acc[nf][0] + bias.x, acc[nf][1] + bias.y);
                    *(float2*)&g_P[(long long)n1 * 256 + o] = r;
                }
                if (n2 < N) {
                    float2 r = make_float2(acc[nf][2] + bias.x, acc[nf][3] + bias.y);
                    *(float2*)&g_P[(long long)n2 * 256 + o] = r;
                }
            }
        }
        __syncwarp();   // own A-tile reads done before next tile's stores
    }
}

// ---------------------------------------------------------------------------
// Kernel 2: persistent HMMA fp16 2-pass, 128-edge tiles, 8 independent
// warps x 16 edges, 256 thr, 2 blocks/SM. XOR addresses, index prefetch.
// ---------------------------------------------------------------------------
#define A_HI_OFF 0
#define A_LO_OFF 32768
#define B_HI_OFF 65536
#define SBW_OFF  81920
#define EDGE_SMEM_BYTES (81920 + 512 + 1024)

__global__ __launch_bounds__(256, 2)
void edge_kernel(const int* __restrict__ eidx_w,
                 const float* __restrict__ W2,
                 const float* __restrict__ b2,
                 const float* __restrict__ W3,
                 const float* __restrict__ b3,
                 float* __restrict__ out, int E, int N, int nTiles) {
    extern __shared__ char smem_raw[];
    char* sm = (char*)(((uintptr_t)smem_raw + 1023) & ~(uintptr_t)1023);
    const uint32_t sbase = smem_u32(sm);
    float4* sBW4 = (float4*)(sm + SBW_OFF);
    __shared__ int sAny;

    const int tid  = threadIdx.x;
    const int lane = tid & 31, w = tid >> 5;

    // ---- one-time: dtype detect, W2 fp16 staging, b2/W3 staging ----
    if (tid == 0) sAny = 0;
    __syncthreads();
    if (tid < 64 && eidx_w[2 * tid + 1] != 0) atomicOr(&sAny, 1);

#pragma unroll 4
    for (int it = 0; it < 32; it++) {
        int slot = it * 256 + tid;
        int k = slot >> 6, o = slot & 63;
        __half hv = __float2half_rn(W2[k * 64 + o]);
        uint32_t off = SWZ((uint32_t)(k * 128 + o * 2));
        *(__half*)(sm + B_HI_OFF + off) = hv;
    }
    if (tid < 32)
        sBW4[tid] = make_float4(b2[2 * tid], W3[2 * tid],
                                b2[2 * tid + 1], W3[2 * tid + 1]);
    __syncthreads();

    const int stride = sAny ? 1 : 2;
    const float bias3 = __ldg(&b3[0]);
    const char* Pb = (const char*)g_P;
    const int grid = gridDim.x;

    // ---- fragment geometry + XOR-compressed bases ----
    const int aHalf = (lane >> 4) * 16;
    const int bKrow = (lane & 7) + ((lane >> 3) & 1) * 8;
    const int bHalf = (lane >> 4) * 16;
    const int g = lane >> 2, tq = lane & 3;

    const uint32_t Ra = (uint32_t)((w * 16 + (lane & 15)) * 128);
    const uint32_t aBase0 = sbase + A_HI_OFF + Ra
                          + ((uint32_t)aHalf ^ ((Ra >> 3) & 0x70));
    const uint32_t Rb = (uint32_t)(bKrow * 128);
    const uint32_t bBase0 = sbase + B_HI_OFF + Rb
                          + ((uint32_t)bHalf ^ ((Rb >> 3) & 0x70));

    // index loader (warp w owns edges t*128 + w*16 .. +15)
    auto load_idx = [&](int t) -> int {
        int l = lane & 15;
        int e = t * 128 + w * 16 + l; if (e >= E) e = E - 1;
        long long off = (lane < 16) ? (long long)e * stride
                                    : ((long long)E + e) * stride;
        int v = eidx_w[off];
        return min(max(v, 0), N - 1);
    };

    int t = blockIdx.x;
    int myidx = (t < nTiles) ? load_idx(t) : 0;

    for (; t < nTiles; t += grid) {
        // ---- gather + relu + fp16 hi/lo -> own 16 A rows ----
#pragma unroll 4
        for (int i = 0; i < 16; i++) {
            int si = __shfl_sync(0xffffffffu, myidx, i);
            int di = __shfl_sync(0xffffffffu, myidx, 16 + i);
            float4 a = __ldg((const float4*)(Pb + (uint32_t)si * 1024u
                                                + (uint32_t)(lane * 16)));
            float4 b = __ldg((const float4*)(Pb + (uint32_t)di * 1024u + 512u
                                                + (uint32_t)(lane * 16)));
            float4 h;
            h.x = fmaxf(a.x + b.x, 0.f);
            h.y = fmaxf(a.y + b.y, 0.f);
            h.z = fmaxf(a.z + b.z, 0.f);
            h.w = fmaxf(a.w + b.w, 0.f);
            uint2 uhi, ulo;
            split4(h, uhi, ulo);

            int row = w * 16 + i;
            int sub = lane >> 4;
            uint32_t boff = SWZ((uint32_t)(row * 128 + (lane & 15) * 8));
            char* pa = sm + sub * 16384 + boff;
            *(uint2*)(pa + A_HI_OFF) = uhi;
            *(uint2*)(pa + A_LO_OFF) = ulo;
        }
        __syncwarp();

        // ---- prefetch next tile's indices (hidden under MMA) ----
        int tn = t + grid;
        int nextidx = (tn < nTiles) ? load_idx(tn) : 0;

        // ---- fp16 2-pass GEMM: Ah·Bh + Al·Bh ----
        float acc[8][4];
#pragma unroll
        for (int nf = 0; nf < 8; nf++)
#pragma unroll
            for (int p = 0; p < 4; p++) acc[nf][p] = 0.f;

#pragma unroll
        for (int ks = 0; ks < 8; ks++) {
            uint32_t a_hi[4], a_lo[4];
            uint32_t aA = (aBase0 + ((ks >> 2) * 16384)) ^ ((ks & 3) << 5);
            ldsm4(a_hi, aA);
            ldsm4(a_lo, aA + 32768);
            uint32_t bRow = bBase0 + (uint32_t)(ks * 2048);
#pragma unroll
            for (int nb = 0; nb < 4; nb++) {
                uint32_t bh[4];
                ldsm4t(bh, bRow ^ (nb << 5));
                mma16816(acc[2 * nb],     a_hi, bh[0], bh[1]);
                mma16816(acc[2 * nb + 1], a_hi, bh[2], bh[3]);
                mma16816(acc[2 * nb],     a_lo, bh[0], bh[1]);
                mma16816(acc[2 * nb + 1], a_lo, bh[2], bh[3]);
            }
        }

        // ---- epilogue: +b2, relu, dot W3, 4-lane reduce, store ----
        float s1 = 0.f, s2 = 0.f;
#pragma unroll
        for (int nf = 0; nf < 8; nf++) {
            float4 bw = sBW4[nf * 4 + tq];
            s1 += fmaxf(acc[nf][0] + bw.x, 0.f) * bw.y
                + fmaxf(acc[nf][1] + bw.z, 0.f) * bw.w;
            s2 += fmaxf(acc[nf][2] + bw.x, 0.f) * bw.y
                + fmaxf(acc[nf][3] + bw.z, 0.f) * bw.w;
        }
        s1 += __shfl_xor_sync(0xffffffffu, s1, 1);
        s1 += __shfl_xor_sync(0xffffffffu, s1, 2);
        s2 += __shfl_xor_sync(0xffffffffu, s2, 1);
        s2 += __shfl_xor_sync(0xffffffffu, s2, 2);
        if (tq == 0) {
            int e1 = t * 128 + w * 16 + g;
            int e2 = e1 + 8;
            if (e1 < E) out[e1] = s1 + bias3;
            if (e2 < E) out[e2] = s2 + bias3;
        }
        myidx = nextidx;
        __syncwarp();   // fragment reads done before next tile's A stores
    }
}

// ---------------------------------------------------------------------------
extern "C" void kernel_launch(void* const* d_in, const int* in_sizes, int n_in,
                              void* d_out, int out_size) {
    const float* emb    = (const float*)d_in[0];
    const int*   eidx_w = (const int*)d_in[1];
    const float* W1     = (const float*)d_in[2];
    const float* b1     = (const float*)d_in[3];
    const float* W2     = (const float*)d_in[4];
    const float* b2     = (const float*)d_in[5];
    const float* W3     = (const float*)d_in[6];
    const float* b3     = (const float*)d_in[7];

    int N = in_sizes[0] / 128;
    int E = in_sizes[1] / 2;
    int nTilesP = (N + 127) / 128;
    int nTilesE = (E + 127) / 128;

    static int smem_set = 0;
    if (!smem_set) {
        cudaFuncSetAttribute(precompute_kernel,
                             cudaFuncAttributeMaxDynamicSharedMemorySize,
                             PRE_SMEM_BYTES);
        cudaFuncSetAttribute(edge_kernel,
                             cudaFuncAttributeMaxDynamicSharedMemorySize,
                             EDGE_SMEM_BYTES);
        smem_set = 1;
    }

    precompute_kernel<<<NSM, 256, PRE_SMEM_BYTES>>>(emb, W1, b1, N, nTilesP);
    edge_kernel<<<2 * NSM, 256, EDGE_SMEM_BYTES>>>(eidx_w, W2, b2, W3, b3,
                                                   (float*)d_out, E, N, nTilesE);
}

// round 15
// speedup vs baseline: 2.5068x; 1.4827x over previous
#include <cuda_runtime.h>
#include <cuda_fp16.h>
#include <cstdint>

// ---------------------------------------------------------------------------
// LinkWeightDecoder: out[e] = MLP(concat(emb[src_e], emb[dst_e]))
//   Single-pass fp16 HMMA everywhere (deterministic seed -> stable rel_err):
//   K1: P[n] = fp16( emb[n] @ [W1a|W1b] + b1-fold )   (P stored fp16, 51 MB,
//       fully L2-resident)
//   K2: h1 = relu_fp16(Psrc + Pdst); D = h1 @ W2 (fp32 acc);
//       out[e] = sum_j relu(D[e][j]+b2[j])*W3[j] + b3.
//   128-row tiles, 8 independent warps x 16 rows, XOR-compressed addresses.
// ---------------------------------------------------------------------------

#define MAXN 100000
#define NSM  148

__device__ __half g_P[MAXN * 256];   // per-node projections, fp16 (51.2 MB)

// ---------------- helpers ----------------
__device__ __forceinline__ uint32_t smem_u32(const void* p) {
    uint32_t a;
    asm("{ .reg .u64 t; cvta.to.shared.u64 t, %1; cvt.u32.u64 %0, t; }"
        : "=r"(a) : "l"(p));
    return a;
}
#define SWZ(off) ((off) ^ (((off) >> 3) & 0x70))

__device__ __forceinline__ void ldsm4(uint32_t* r, uint32_t addr) {
    asm volatile("ldmatrix.sync.aligned.m8n8.x4.shared.b16 {%0,%1,%2,%3}, [%4];"
        : "=r"(r[0]), "=r"(r[1]), "=r"(r[2]), "=r"(r[3]) : "r"(addr));
}
__device__ __forceinline__ void ldsm4t(uint32_t* r, uint32_t addr) {
    asm volatile("ldmatrix.sync.aligned.m8n8.x4.trans.shared.b16 {%0,%1,%2,%3}, [%4];"
        : "=r"(r[0]), "=r"(r[1]), "=r"(r[2]), "=r"(r[3]) : "r"(addr));
}
__device__ __forceinline__ void mma16816(float* c, const uint32_t* a,
                                         uint32_t b0, uint32_t b1) {
    asm volatile(
        "mma.sync.aligned.m16n8k16.row.col.f32.f16.f16.f32 "
        "{%0,%1,%2,%3}, {%4,%5,%6,%7}, {%8,%9}, {%0,%1,%2,%3};"
        : "+f"(c[0]), "+f"(c[1]), "+f"(c[2]), "+f"(c[3])
        : "r"(a[0]), "r"(a[1]), "r"(a[2]), "r"(a[3]), "r"(b0), "r"(b1));
}
// round fp32 quad -> single fp16 packed uint2
__device__ __forceinline__ uint2 pack4h(float4 v) {
    __half2 p01 = __float22half2_rn(make_float2(v.x, v.y));
    __half2 p23 = __float22half2_rn(make_float2(v.z, v.w));
    uint2 u;
    u.x = *(uint32_t*)&p01; u.y = *(uint32_t*)&p23;
    return u;
}

// ---------------------------------------------------------------------------
// Kernel 1 (persistent, HMMA fp16 single-pass): P = fp16(emb @ [W1a|W1b] + b1)
// 128-node tiles, 8 independent warps x 16 rows, 2 blocks/SM.
// SMEM: A fp16 [128r x 128k] 2 subtiles @0 (32 KB); B fp16 4 chunk-tiles
//       [128k x 64n] @32768 (64 KB); sB1 @98304.
// ---------------------------------------------------------------------------
#define PA_HI 0
#define PB_HI 32768
#define PB1   98304
#define PRE_SMEM_BYTES (98304 + 1024 + 1024)

__global__ __launch_bounds__(256, 2)
void precompute_kernel(const float* __restrict__ emb,
                       const float* __restrict__ W1,
                       const float* __restrict__ b1, int N, int nTiles) {
    extern __shared__ char smem_raw[];
    char* sm = (char*)(((uintptr_t)smem_raw + 1023) & ~(uintptr_t)1023);
    const uint32_t sbase = smem_u32(sm);
    float* sB1 = (float*)(sm + PB1);

    const int tid  = threadIdx.x;
    const int lane = tid & 31, w = tid >> 5;

    // ---- one-time: stage W1eff fp16 (4 chunk-tiles of [128k x 64n]) ----
#pragma unroll 4
    for (int it = 0; it < 32; it++) {
        int idx = it * 256 + tid;
        int k = idx >> 6, og4 = (idx & 63) * 4;
        const float* sp = (og4 < 128) ? &W1[k * 128 + og4]
                                      : &W1[(k + 128) * 128 + (og4 - 128)];
        float4 v = *(const float4*)sp;
        int c = og4 >> 6, o = og4 & 63;
        uint32_t off = c * 16384 + SWZ((uint32_t)(k * 128 + o * 2));
        *(uint2*)(sm + PB_HI + off) = pack4h(v);
    }
    sB1[tid] = (tid < 128) ? b1[tid] : 0.f;
    __syncthreads();

    // ---- fragment geometry + XOR-compressed bases ----
    const int aHalf = (lane >> 4) * 16;
    const int bKrow = (lane & 7) + ((lane >> 3) & 1) * 8;
    const int bHalf = (lane >> 4) * 16;
    const int g = lane >> 2, tq = lane & 3;

    const uint32_t Ra = (uint32_t)((w * 16 + (lane & 15)) * 128);
    const uint32_t aBase0 = sbase + PA_HI + Ra
                          + ((uint32_t)aHalf ^ ((Ra >> 3) & 0x70));
    const uint32_t Rb = (uint32_t)(bKrow * 128);
    const uint32_t bBaseC = sbase + PB_HI + Rb
                          + ((uint32_t)bHalf ^ ((Rb >> 3) & 0x70));

    const float4* E4 = (const float4*)emb;
    const int grid = gridDim.x;

    for (int t = blockIdx.x; t < nTiles; t += grid) {
        // ---- stage own 16 rows (emb fp32 -> fp16 single) ----
#pragma unroll 4
        for (int i = 0; i < 16; i++) {
            int row = w * 16 + i;
            int node = t * 128 + row; if (node >= N) node = N - 1;
            float4 v = __ldg(&E4[(long long)node * 32 + lane]);
            int sub = lane >> 4;
            uint32_t boff = SWZ((uint32_t)(row * 128 + (lane & 15) * 8));
            *(uint2*)(sm + sub * 16384 + boff) = pack4h(v);
        }
        __syncwarp();

        // ---- hoist A fragments once per tile (chunk-invariant) ----
        uint32_t Ahi[8][4];
#pragma unroll
        for (int ks = 0; ks < 8; ks++) {
            uint32_t aA = (aBase0 + ((ks >> 2) * 16384)) ^ ((ks & 3) << 5);
            ldsm4(Ahi[ks], aA);
        }

        // ---- 4 n-chunks of 64 cols, fp16 single-pass GEMM each ----
        const int n1 = t * 128 + w * 16 + g;
        const int n2 = n1 + 8;
#pragma unroll 1
        for (int c = 0; c < 4; c++) {
            const uint32_t bBase0 = bBaseC + (uint32_t)(c * 16384);

            float acc[8][4];
#pragma unroll
            for (int nf = 0; nf < 8; nf++)
#pragma unroll
                for (int p = 0; p < 4; p++) acc[nf][p] = 0.f;

#pragma unroll
            for (int ks = 0; ks < 8; ks++) {
                uint32_t bRow = bBase0 + (uint32_t)(ks * 2048);
#pragma unroll
                for (int nb = 0; nb < 4; nb++) {
                    uint32_t bh[4];
                    ldsm4t(bh, bRow ^ (nb << 5));
                    mma16816(acc[2 * nb],     Ahi[ks], bh[0], bh[1]);
                    mma16816(acc[2 * nb + 1], Ahi[ks], bh[2], bh[3]);
                }
            }

            // ---- epilogue: +b1 (cols<128), store fp16 pairs to g_P ----
#pragma unroll
            for (int nf = 0; nf < 8; nf++) {
                int o = c * 64 + nf * 8 + tq * 2;
                float2 bias = *(const float2*)&sB1[o];
                if (n1 < N) {
                    __half2 r = __floats2half2_rn(acc[nf][0] + bias.x,
                                                  acc[nf][1] + bias.y);
                    *(__half2*)&g_P[(long long)n1 * 256 + o] = r;
                }
                if (n2 < N) {
                    __half2 r = __floats2half2_rn(acc[nf][2] + bias.x,
                                                  acc[nf][3] + bias.y);
                    *(__half2*)&g_P[(long long)n2 * 256 + o] = r;
                }
            }
        }
        __syncwarp();   // own A-tile reads done before next tile's stores
    }
}

// ---------------------------------------------------------------------------
// Kernel 2: persistent HMMA fp16 single-pass, 128-edge tiles, 8 independent
// warps x 16 edges, 256 thr, 2 blocks/SM. fp16 gather (hadd2/hmax2), XOR
// addresses, index prefetch.
// SMEM: A fp16 @0 (32 KB, 2 subtiles); B (W2) fp16 @32768 (16 KB); sBW @49152.
// ---------------------------------------------------------------------------
#define A_HI_OFF 0
#define B_HI_OFF 32768
#define SBW_OFF  49152
#define EDGE_SMEM_BYTES (49152 + 512 + 1024)

__global__ __launch_bounds__(256, 2)
void edge_kernel(const int* __restrict__ eidx_w,
                 const float* __restrict__ W2,
                 const float* __restrict__ b2,
                 const float* __restrict__ W3,
                 const float* __restrict__ b3,
                 float* __restrict__ out, int E, int N, int nTiles) {
    extern __shared__ char smem_raw[];
    char* sm = (char*)(((uintptr_t)smem_raw + 1023) & ~(uintptr_t)1023);
    const uint32_t sbase = smem_u32(sm);
    float4* sBW4 = (float4*)(sm + SBW_OFF);
    __shared__ int sAny;

    const int tid  = threadIdx.x;
    const int lane = tid & 31, w = tid >> 5;

    // ---- one-time: dtype detect, W2 fp16 staging, b2/W3 staging ----
    if (tid == 0) sAny = 0;
    __syncthreads();
    if (tid < 64 && eidx_w[2 * tid + 1] != 0) atomicOr(&sAny, 1);

#pragma unroll 4
    for (int it = 0; it < 32; it++) {
        int slot = it * 256 + tid;
        int k = slot >> 6, o = slot & 63;
        __half hv = __float2half_rn(W2[k * 64 + o]);
        uint32_t off = SWZ((uint32_t)(k * 128 + o * 2));
        *(__half*)(sm + B_HI_OFF + off) = hv;
    }
    if (tid < 32)
        sBW4[tid] = make_float4(b2[2 * tid], W3[2 * tid],
                                b2[2 * tid + 1], W3[2 * tid + 1]);
    __syncthreads();

    const int stride = sAny ? 1 : 2;
    const float bias3 = __ldg(&b3[0]);
    const char* Pb = (const char*)g_P;
    const int grid = gridDim.x;

    // ---- fragment geometry + XOR-compressed bases ----
    const int aHalf = (lane >> 4) * 16;
    const int bKrow = (lane & 7) + ((lane >> 3) & 1) * 8;
    const int bHalf = (lane >> 4) * 16;
    const int g = lane >> 2, tq = lane & 3;

    const uint32_t Ra = (uint32_t)((w * 16 + (lane & 15)) * 128);
    const uint32_t aBase0 = sbase + A_HI_OFF + Ra
                          + ((uint32_t)aHalf ^ ((Ra >> 3) & 0x70));
    const uint32_t Rb = (uint32_t)(bKrow * 128);
    const uint32_t bBase0 = sbase + B_HI_OFF + Rb
                          + ((uint32_t)bHalf ^ ((Rb >> 3) & 0x70));

    // index loader (warp w owns edges t*128 + w*16 .. +15)
    auto load_idx = [&](int t) -> int {
        int l = lane & 15;
        int e = t * 128 + w * 16 + l; if (e >= E) e = E - 1;
        long long off = (lane < 16) ? (long long)e * stride
                                    : ((long long)E + e) * stride;
        int v = eidx_w[off];
        return min(max(v, 0), N - 1);
    };

    int t = blockIdx.x;
    int myidx = (t < nTiles) ? load_idx(t) : 0;

    const __half2 hz = __float2half2_rn(0.f);

    for (; t < nTiles; t += grid) {
        // ---- fp16 gather + hadd2/hmax2 relu -> own 16 A rows ----
#pragma unroll 4
        for (int i = 0; i < 16; i++) {
            int si = __shfl_sync(0xffffffffu, myidx, i);
            int di = __shfl_sync(0xffffffffu, myidx, 16 + i);
            uint2 ua = __ldg((const uint2*)(Pb + (uint32_t)si * 512u
                                               + (uint32_t)(lane * 8)));
            uint2 ub = __ldg((const uint2*)(Pb + (uint32_t)di * 512u + 256u
                                               + (uint32_t)(lane * 8)));
            __half2 a0 = *(__half2*)&ua.x, a1 = *(__half2*)&ua.y;
            __half2 b0 = *(__half2*)&ub.x, b1h = *(__half2*)&ub.y;
            __half2 h0 = __hmax2(__hadd2(a0, b0), hz);
            __half2 h1v = __hmax2(__hadd2(a1, b1h), hz);
            uint2 uh;
            uh.x = *(uint32_t*)&h0; uh.y = *(uint32_t*)&h1v;

            int row = w * 16 + i;
            int sub = lane >> 4;
            uint32_t boff = SWZ((uint32_t)(row * 128 + (lane & 15) * 8));
            *(uint2*)(sm + sub * 16384 + boff) = uh;
        }
        __syncwarp();

        // ---- prefetch next tile's indices (hidden under MMA) ----
        int tn = t + grid;
        int nextidx = (tn < nTiles) ? load_idx(tn) : 0;

        // ---- fp16 single-pass GEMM: D = A·B ----
        float acc[8][4];
#pragma unroll
        for (int nf = 0; nf < 8; nf++)
#pragma unroll
            for (int p = 0; p < 4; p++) acc[nf][p] = 0.f;

#pragma unroll
        for (int ks = 0; ks < 8; ks++) {
            uint32_t a_hi[4];
            uint32_t aA = (aBase0 + ((ks >> 2) * 16384)) ^ ((ks & 3) << 5);
            ldsm4(a_hi, aA);
            uint32_t bRow = bBase0 + (uint32_t)(ks * 2048);
#pragma unroll
            for (int nb = 0; nb < 4; nb++) {
                uint32_t bh[4];
                ldsm4t(bh, bRow ^ (nb << 5));
                mma16816(acc[2 * nb],     a_hi, bh[0], bh[1]);
                mma16816(acc[2 * nb + 1], a_hi, bh[2], bh[3]);
            }
        }

        // ---- epilogue: +b2, relu, dot W3, 4-lane reduce, store ----
        float s1 = 0.f, s2 = 0.f;
#pragma unroll
        for (int nf = 0; nf < 8; nf++) {
            float4 bw = sBW4[nf * 4 + tq];
            s1 += fmaxf(acc[nf][0] + bw.x, 0.f) * bw.y
                + fmaxf(acc[nf][1] + bw.z, 0.f) * bw.w;
            s2 += fmaxf(acc[nf][2] + bw.x, 0.f) * bw.y
                + fmaxf(acc[nf][3] + bw.z, 0.f) * bw.w;
        }
        s1 += __shfl_xor_sync(0xffffffffu, s1, 1);
        s1 += __shfl_xor_sync(0xffffffffu, s1, 2);
        s2 += __shfl_xor_sync(0xffffffffu, s2, 1);
        s2 += __shfl_xor_sync(0xffffffffu, s2, 2);
        if (tq == 0) {
            int e1 = t * 128 + w * 16 + g;
            int e2 = e1 + 8;
            if (e1 < E) out[e1] = s1 + bias3;
            if (e2 < E) out[e2] = s2 + bias3;
        }
        myidx = nextidx;
        __syncwarp();   // fragment reads done before next tile's A stores
    }
}

// ---------------------------------------------------------------------------
extern "C" void kernel_launch(void* const* d_in, const int* in_sizes, int n_in,
                              void* d_out, int out_size) {
    const float* emb    = (const float*)d_in[0];
    const int*   eidx_w = (const int*)d_in[1];
    const float* W1     = (const float*)d_in[2];
    const float* b1     = (const float*)d_in[3];
    const float* W2     = (const float*)d_in[4];
    const float* b2     = (const float*)d_in[5];
    const float* W3     = (const float*)d_in[6];
    const float* b3     = (const float*)d_in[7];

    int N = in_sizes[0] / 128;
    int E = in_sizes[1] / 2;
    int nTilesP = (N + 127) / 128;
    int nTilesE = (E + 127) / 128;

    static int smem_set = 0;
    if (!smem_set) {
        cudaFuncSetAttribute(precompute_kernel,
                             cudaFuncAttributeMaxDynamicSharedMemorySize,
                             PRE_SMEM_BYTES);
        cudaFuncSetAttribute(edge_kernel,
                             cudaFuncAttributeMaxDynamicSharedMemorySize,
                             EDGE_SMEM_BYTES);
        smem_set = 1;
    }

    precompute_kernel<<<2 * NSM, 256, PRE_SMEM_BYTES>>>(emb, W1, b1, N, nTilesP);
    edge_kernel<<<2 * NSM, 256, EDGE_SMEM_BYTES>>>(eidx_w, W2, b2, W3, b3,
                                                   (float*)d_out, E, N, nTilesE);
}